// round 2
// baseline (speedup 1.0000x reference)
#include <cuda_runtime.h>
#include <cuda_bf16.h>
#include <cstdint>

// Problem constants
#define NTOK 8192
#define DDIM 1024
#define HDIM 4096
#define NEXP 8
#define TOPK 2
#define CAP  2048          // (TOPK*NTOK)/NEXP
#define SLOTS (TOPK*NTOK)  // 16384

// ---------------- scratch (__device__ globals: allocation-free) ----------------
__device__ float g_scores[NTOK * NEXP];          // softmax probs [N,E]
__device__ float g_topv[NTOK * TOPK];
__device__ int   g_topi[NTOK * TOPK];
__device__ int   g_pos[SLOTS];                   // slot-major positions
__device__ int   g_s2t[NEXP * CAP];              // expert slot -> token (-1 empty)
__device__ int   g_ce[NEXP];                     // top-1 counts
__device__ float g_h[(size_t)NEXP * CAP * HDIM]; // 256 MB intermediate
__device__ float g_y[(size_t)NEXP * CAP * DDIM]; // 64 MB expert outputs

// ---------------- init ----------------
__global__ void init_kernel() {
    int i = blockIdx.x * blockDim.x + threadIdx.x;
    if (i < NEXP * CAP) g_s2t[i] = -1;
    if (i < NEXP)       g_ce[i]  = 0;
}

// ---------------- gate: logits -> softmax -> top2 ----------------
__global__ void gate_kernel(const float* __restrict__ x, const float* __restrict__ wg) {
    int gwarp = (blockIdx.x * blockDim.x + threadIdx.x) >> 5;
    int lane  = threadIdx.x & 31;
    if (gwarp >= NTOK) return;
    const float* xr = x + (size_t)gwarp * DDIM;
    float acc[NEXP];
#pragma unroll
    for (int e = 0; e < NEXP; e++) acc[e] = 0.f;
#pragma unroll 4
    for (int i = 0; i < DDIM / 32; i++) {
        int d = lane + 32 * i;
        float xv = xr[d];
        const float* wr = wg + d * NEXP;
#pragma unroll
        for (int e = 0; e < NEXP; e++) acc[e] = fmaf(xv, wr[e], acc[e]);
    }
#pragma unroll
    for (int off = 16; off > 0; off >>= 1)
#pragma unroll
        for (int e = 0; e < NEXP; e++)
            acc[e] += __shfl_xor_sync(0xffffffffu, acc[e], off);

    if (lane == 0) {
        float m = acc[0];
#pragma unroll
        for (int e = 1; e < NEXP; e++) m = fmaxf(m, acc[e]);
        float p[NEXP]; float s = 0.f;
#pragma unroll
        for (int e = 0; e < NEXP; e++) { p[e] = expf(acc[e] - m); s += p[e]; }
        float inv = 1.f / s;
#pragma unroll
        for (int e = 0; e < NEXP; e++) { p[e] *= inv; g_scores[gwarp * NEXP + e] = p[e]; }
        // top-1 (ties -> lowest index, matching lax.top_k)
        int i1 = 0; float v1 = p[0];
#pragma unroll
        for (int e = 1; e < NEXP; e++) if (p[e] > v1) { v1 = p[e]; i1 = e; }
        int i2 = -1; float v2 = -1.f;
#pragma unroll
        for (int e = 0; e < NEXP; e++) if (e != i1 && p[e] > v2) { v2 = p[e]; i2 = e; }
        g_topv[gwarp * 2 + 0] = v1; g_topv[gwarp * 2 + 1] = v2;
        g_topi[gwarp * 2 + 0] = i1; g_topi[gwarp * 2 + 1] = i2;
        atomicAdd(&g_ce[i1], 1);
    }
}

// ---------------- routing: deterministic slot-major scan ----------------
__global__ void route_kernel() {
    const int T = 512, PER = SLOTS / T;  // 32
    int t = threadIdx.x;
    int lane = t & 31, w = t >> 5;       // 16 warps
    int base = t * PER;

    int cnt[NEXP];
#pragma unroll
    for (int e = 0; e < NEXP; e++) cnt[e] = 0;
    int myexp[PER];
#pragma unroll
    for (int i = 0; i < PER; i++) {
        int s = base + i;
        int slot = s >> 13;       // s / NTOK
        int n = s & (NTOK - 1);
        int e = g_topi[n * 2 + slot];
        myexp[i] = e;
        cnt[e]++;
    }
    int inc[NEXP];
#pragma unroll
    for (int e = 0; e < NEXP; e++) inc[e] = cnt[e];
#pragma unroll
    for (int o = 1; o < 32; o <<= 1) {
#pragma unroll
        for (int e = 0; e < NEXP; e++) {
            int v = __shfl_up_sync(0xffffffffu, inc[e], o);
            if (lane >= o) inc[e] += v;
        }
    }
    __shared__ int wtot[16][NEXP], wexcl[16][NEXP];
    if (lane == 31)
#pragma unroll
        for (int e = 0; e < NEXP; e++) wtot[w][e] = inc[e];
    __syncthreads();
    if (t == 0) {
        int run[NEXP];
#pragma unroll
        for (int e = 0; e < NEXP; e++) run[e] = 0;
        for (int ww = 0; ww < 16; ww++)
#pragma unroll
            for (int e = 0; e < NEXP; e++) { wexcl[ww][e] = run[e]; run[e] += wtot[ww][e]; }
    }
    __syncthreads();
    int off[NEXP];
#pragma unroll
    for (int e = 0; e < NEXP; e++) off[e] = wexcl[w][e] + inc[e] - cnt[e];
#pragma unroll
    for (int i = 0; i < PER; i++) {
        int e = myexp[i];
        int p = off[e]++;
        int s = base + i;
        g_pos[s] = p;
        if (p < CAP) {
            int n = s & (NTOK - 1);
            g_s2t[e * CAP + p] = n;
        }
    }
}

// ---------------- tf32x3 mma GEMM ----------------
#define BM 128
#define BN 128
#define BK 16
#define BKP 20    // pad -> conflict-free A frag loads
#define BNP 136   // pad -> conflict-free B frag loads

__device__ __forceinline__ void cp16(uint32_t dst, const void* src, int bytes) {
    asm volatile("cp.async.cg.shared.global [%0], [%1], 16, %2;\n"
                 :: "r"(dst), "l"(src), "r"(bytes));
}
__device__ __forceinline__ void cp_commit() { asm volatile("cp.async.commit_group;\n" ::); }
__device__ __forceinline__ void cp_wait0()  { asm volatile("cp.async.wait_group 0;\n" ::); }

__device__ __forceinline__ void mma_tf32(float* d, const uint32_t* a, const uint32_t* b) {
    asm volatile(
        "mma.sync.aligned.m16n8k8.row.col.f32.tf32.tf32.f32 "
        "{%0,%1,%2,%3}, {%4,%5,%6,%7}, {%8,%9}, {%0,%1,%2,%3};\n"
        : "+f"(d[0]), "+f"(d[1]), "+f"(d[2]), "+f"(d[3])
        : "r"(a[0]), "r"(a[1]), "r"(a[2]), "r"(a[3]), "r"(b[0]), "r"(b[1]));
}

// split fp32 v -> (hi tf32 bits, lo residual bits)
__device__ __forceinline__ void tf32_split(float v, uint32_t& hi, uint32_t& lo) {
    uint32_t h;
    asm("cvt.rna.tf32.f32 %0, %1;\n" : "=r"(h) : "f"(v));
    hi = h;
    lo = __float_as_uint(v - __uint_as_float(h));
}

// PHASE1: A = gather(x) via g_s2t, B = fc1_w, C = g_h, relu(+bias)
// PHASE2: A = g_h,                B = fc2_w, C = g_y, +bias
template<int KD, int ND, bool PHASE1>
__global__ void __launch_bounds__(256) gemm_kernel(
    const float* __restrict__ Ax,
    const float* __restrict__ B,
    const float* __restrict__ bias)
{
    __shared__ float As[2][BM][BKP];
    __shared__ float Bs[2][BK][BNP];
    const int e  = blockIdx.z;
    const int m0 = blockIdx.y * BM;
    const int n0 = blockIdx.x * BN;
    const float* A  = PHASE1 ? Ax : (const float*)g_h;
    const float* Be = B + (size_t)e * KD * ND;
    float* Ce       = (PHASE1 ? g_h : g_y) + (size_t)e * CAP * ND;
    const float* be = bias + (size_t)e * ND;

    const int tid = threadIdx.x;
    uint32_t as_base = (uint32_t)__cvta_generic_to_shared(&As[0][0][0]);
    uint32_t bs_base = (uint32_t)__cvta_generic_to_shared(&Bs[0][0][0]);

    const float* aptr[2]; int abytes[2]; uint32_t adst[2];
#pragma unroll
    for (int i = 0; i < 2; i++) {
        int c = tid + i * 256;
        int row = c >> 2;
        int kc  = (c & 3) * 4;
        adst[i] = as_base + (uint32_t)((row * BKP + kc) * 4);
        if (PHASE1) {
            int tok = g_s2t[e * CAP + m0 + row];
            abytes[i] = (tok >= 0) ? 16 : 0;
            aptr[i] = (tok >= 0) ? (A + (size_t)tok * KD + kc) : A;
        } else {
            abytes[i] = 16;
            aptr[i] = A + (size_t)(e * CAP + m0 + row) * KD + kc;
        }
    }
    const float* bptr[2]; uint32_t bdst[2];
#pragma unroll
    for (int i = 0; i < 2; i++) {
        int c = tid + i * 256;
        int kr = c >> 5;
        int nc = (c & 31) * 4;
        bdst[i] = bs_base + (uint32_t)((kr * BNP + nc) * 4);
        bptr[i] = Be + (size_t)kr * ND + n0 + nc;
    }
    const uint32_t aStride = BM * BKP * 4;
    const uint32_t bStride = BK * BNP * 4;

    auto load_stage = [&](int buf, int kt) {
#pragma unroll
        for (int i = 0; i < 2; i++)
            cp16(adst[i] + buf * aStride, aptr[i] + (size_t)kt * BK, abytes[i]);
#pragma unroll
        for (int i = 0; i < 2; i++)
            cp16(bdst[i] + buf * bStride, bptr[i] + (size_t)kt * BK * ND, 16);
        cp_commit();
    };

    const int warp = tid >> 5, lane = tid & 31;
    const int wm = warp >> 2, wn = warp & 3;   // 2 x 4 warps
    const int mb = wm * 64, nb = wn * 32;      // warp tile 64x32
    const int lr = lane >> 2, lc = lane & 3;

    float acc[4][4][4];
#pragma unroll
    for (int mi = 0; mi < 4; mi++)
#pragma unroll
        for (int ni = 0; ni < 4; ni++)
#pragma unroll
            for (int r = 0; r < 4; r++) acc[mi][ni][r] = 0.f;

    load_stage(0, 0);
    const int KT = KD / BK;
    for (int kt = 0; kt < KT; kt++) {
        cp_wait0();
        __syncthreads();
        int buf = kt & 1;
        if (kt + 1 < KT) load_stage(buf ^ 1, kt + 1);
#pragma unroll
        for (int ks = 0; ks < 2; ks++) {
            uint32_t afh[4][4], afl[4][4];
#pragma unroll
            for (int mi = 0; mi < 4; mi++) {
                const float* p = &As[buf][mb + mi * 16 + lr][ks * 8 + lc];
                tf32_split(p[0],            afh[mi][0], afl[mi][0]);
                tf32_split(p[8 * BKP],      afh[mi][1], afl[mi][1]);
                tf32_split(p[4],            afh[mi][2], afl[mi][2]);
                tf32_split(p[8 * BKP + 4],  afh[mi][3], afl[mi][3]);
            }
            uint32_t bfh[4][2], bfl[4][2];
#pragma unroll
            for (int ni = 0; ni < 4; ni++) {
                const float* q = &Bs[buf][ks * 8 + lc][nb + ni * 8 + lr];
                tf32_split(q[0],        bfh[ni][0], bfl[ni][0]);
                tf32_split(q[4 * BNP],  bfh[ni][1], bfl[ni][1]);
            }
#pragma unroll
            for (int mi = 0; mi < 4; mi++)
#pragma unroll
                for (int ni = 0; ni < 4; ni++) {
                    mma_tf32(acc[mi][ni], afh[mi], bfl[ni]);  // hi*lo
                    mma_tf32(acc[mi][ni], afl[mi], bfh[ni]);  // lo*hi
                    mma_tf32(acc[mi][ni], afh[mi], bfh[ni]);  // hi*hi
                }
        }
        __syncthreads();
    }

    // epilogue: +bias (, relu), store fp32
#pragma unroll
    for (int mi = 0; mi < 4; mi++) {
        int r = m0 + mb + mi * 16 + lr;
#pragma unroll
        for (int ni = 0; ni < 4; ni++) {
            int cb = n0 + nb + ni * 8 + 2 * lc;
            float b0 = be[cb], b1 = be[cb + 1];
            float v0 = acc[mi][ni][0] + b0, v1 = acc[mi][ni][1] + b1;
            float v2 = acc[mi][ni][2] + b0, v3 = acc[mi][ni][3] + b1;
            if (PHASE1) {
                v0 = fmaxf(v0, 0.f); v1 = fmaxf(v1, 0.f);
                v2 = fmaxf(v2, 0.f); v3 = fmaxf(v3, 0.f);
            }
            *(float2*)&Ce[(size_t)r * ND + cb]       = make_float2(v0, v1);
            *(float2*)&Ce[(size_t)(r + 8) * ND + cb] = make_float2(v2, v3);
        }
    }
}

// ---------------- combine: out[n,:] = sum_slot topv * y[flat_idx,:] ----------------
__global__ void combine_kernel(float* __restrict__ out) {
    int n = blockIdx.x, tid = threadIdx.x;
    float4 acc = make_float4(0.f, 0.f, 0.f, 0.f);
#pragma unroll
    for (int slot = 0; slot < TOPK; slot++) {
        int p = g_pos[slot * NTOK + n];
        if (p < CAP) {
            float v = g_topv[n * 2 + slot];
            int e = g_topi[n * 2 + slot];
            const float4* row = (const float4*)(g_y + (size_t)(e * CAP + p) * DDIM);
            float4 f = row[tid];
            acc.x += v * f.x; acc.y += v * f.y; acc.z += v * f.z; acc.w += v * f.w;
        }
    }
    ((float4*)(out + (size_t)n * DDIM))[tid] = acc;
}

// ---------------- aux loss ----------------
__global__ void aux_kernel(float* __restrict__ out, int out_size) {
    __shared__ float s[256];
    int tid = threadIdx.x;
    float p[NEXP];
#pragma unroll
    for (int e = 0; e < NEXP; e++) p[e] = 0.f;
    for (int i = tid; i < NTOK; i += 256)
#pragma unroll
        for (int e = 0; e < NEXP; e++) p[e] += g_scores[i * NEXP + e];

    float total = 0.f;
#pragma unroll
    for (int e = 0; e < NEXP; e++) {
        s[tid] = p[e];
        __syncthreads();
        for (int st = 128; st > 0; st >>= 1) {
            if (tid < st) s[tid] += s[tid + st];
            __syncthreads();
        }
        if (tid == 0) {
            float me = s[0] / (float)NTOK;
            float ce = (float)g_ce[e] / (float)NTOK;
            total += me * ce;
        }
        __syncthreads();
    }
    if (tid == 0) {
        float laux = (float)NEXP * total;
        for (long i = (long)NTOK * DDIM; i < (long)out_size; i++) out[i] = laux;
    }
}

// ---------------- launch ----------------
extern "C" void kernel_launch(void* const* d_in, const int* in_sizes, int n_in,
                              void* d_out, int out_size) {
    const float* x    = (const float*)d_in[0];
    const float* wg   = (const float*)d_in[1];
    const float* fc1w = (const float*)d_in[2];
    const float* fc1b = (const float*)d_in[3];
    const float* fc2w = (const float*)d_in[4];
    const float* fc2b = (const float*)d_in[5];
    float* out = (float*)d_out;
    (void)in_sizes; (void)n_in;

    init_kernel<<<(NEXP * CAP + 255) / 256, 256>>>();
    gate_kernel<<<NTOK / 8, 256>>>(x, wg);
    route_kernel<<<1, 512>>>();
    gemm_kernel<DDIM, HDIM, true ><<<dim3(HDIM / BN, CAP / BM, NEXP), 256>>>(x, fc1w, fc1b);
    gemm_kernel<HDIM, DDIM, false><<<dim3(DDIM / BN, CAP / BM, NEXP), 256>>>(x, fc2w, fc2b);
    combine_kernel<<<NTOK, 256>>>(out);
    aux_kernel<<<1, 256>>>(out, out_size);
}

// round 3
// speedup vs baseline: 1.6321x; 1.6321x over previous
#include <cuda_runtime.h>
#include <cuda_bf16.h>
#include <cstdint>

// Problem constants
#define NTOK 8192
#define DDIM 1024
#define HDIM 4096
#define NEXP 8
#define TOPK 2
#define CAP  2048          // (TOPK*NTOK)/NEXP
#define SLOTS (TOPK*NTOK)  // 16384

// ---------------- scratch (__device__ globals: allocation-free) ----------------
__device__ float g_scores[NTOK * NEXP];          // softmax probs [N,E]
__device__ float g_topv[NTOK * TOPK];
__device__ int   g_topi[NTOK * TOPK];
__device__ int   g_pos[SLOTS];                   // slot-major positions
__device__ int   g_s2t[NEXP * CAP];              // expert slot -> token (-1 empty)
__device__ int   g_ce[NEXP];                     // top-1 counts
__device__ float g_h[(size_t)NEXP * CAP * HDIM]; // 256 MB intermediate
__device__ float g_y[(size_t)NEXP * CAP * DDIM]; // 64 MB expert outputs

// ---------------- init ----------------
__global__ void init_kernel() {
    int i = blockIdx.x * blockDim.x + threadIdx.x;
    if (i < NEXP * CAP) g_s2t[i] = -1;
    if (i < NEXP)       g_ce[i]  = 0;
}

// ---------------- gate: logits -> softmax -> top2 ----------------
__global__ void gate_kernel(const float* __restrict__ x, const float* __restrict__ wg) {
    int gwarp = (blockIdx.x * blockDim.x + threadIdx.x) >> 5;
    int lane  = threadIdx.x & 31;
    if (gwarp >= NTOK) return;
    const float* xr = x + (size_t)gwarp * DDIM;
    float acc[NEXP];
#pragma unroll
    for (int e = 0; e < NEXP; e++) acc[e] = 0.f;
#pragma unroll 4
    for (int i = 0; i < DDIM / 32; i++) {
        int d = lane + 32 * i;
        float xv = xr[d];
        const float* wr = wg + d * NEXP;
#pragma unroll
        for (int e = 0; e < NEXP; e++) acc[e] = fmaf(xv, wr[e], acc[e]);
    }
#pragma unroll
    for (int off = 16; off > 0; off >>= 1)
#pragma unroll
        for (int e = 0; e < NEXP; e++)
            acc[e] += __shfl_xor_sync(0xffffffffu, acc[e], off);

    if (lane == 0) {
        float m = acc[0];
#pragma unroll
        for (int e = 1; e < NEXP; e++) m = fmaxf(m, acc[e]);
        float p[NEXP]; float s = 0.f;
#pragma unroll
        for (int e = 0; e < NEXP; e++) { p[e] = expf(acc[e] - m); s += p[e]; }
        float inv = 1.f / s;
#pragma unroll
        for (int e = 0; e < NEXP; e++) { p[e] *= inv; g_scores[gwarp * NEXP + e] = p[e]; }
        // top-1 (ties -> lowest index, matching lax.top_k)
        int i1 = 0; float v1 = p[0];
#pragma unroll
        for (int e = 1; e < NEXP; e++) if (p[e] > v1) { v1 = p[e]; i1 = e; }
        int i2 = -1; float v2 = -1.f;
#pragma unroll
        for (int e = 0; e < NEXP; e++) if (e != i1 && p[e] > v2) { v2 = p[e]; i2 = e; }
        g_topv[gwarp * 2 + 0] = v1; g_topv[gwarp * 2 + 1] = v2;
        g_topi[gwarp * 2 + 0] = i1; g_topi[gwarp * 2 + 1] = i2;
        atomicAdd(&g_ce[i1], 1);
    }
}

// ---------------- routing: deterministic slot-major scan ----------------
__global__ void route_kernel() {
    const int T = 512, PER = SLOTS / T;  // 32
    int t = threadIdx.x;
    int lane = t & 31, w = t >> 5;       // 16 warps
    int base = t * PER;

    int cnt[NEXP];
#pragma unroll
    for (int e = 0; e < NEXP; e++) cnt[e] = 0;
    int myexp[PER];
#pragma unroll
    for (int i = 0; i < PER; i++) {
        int s = base + i;
        int slot = s >> 13;       // s / NTOK
        int n = s & (NTOK - 1);
        int e = g_topi[n * 2 + slot];
        myexp[i] = e;
        cnt[e]++;
    }
    int inc[NEXP];
#pragma unroll
    for (int e = 0; e < NEXP; e++) inc[e] = cnt[e];
#pragma unroll
    for (int o = 1; o < 32; o <<= 1) {
#pragma unroll
        for (int e = 0; e < NEXP; e++) {
            int v = __shfl_up_sync(0xffffffffu, inc[e], o);
            if (lane >= o) inc[e] += v;
        }
    }
    __shared__ int wtot[16][NEXP], wexcl[16][NEXP];
    if (lane == 31)
#pragma unroll
        for (int e = 0; e < NEXP; e++) wtot[w][e] = inc[e];
    __syncthreads();
    if (t == 0) {
        int run[NEXP];
#pragma unroll
        for (int e = 0; e < NEXP; e++) run[e] = 0;
        for (int ww = 0; ww < 16; ww++)
#pragma unroll
            for (int e = 0; e < NEXP; e++) { wexcl[ww][e] = run[e]; run[e] += wtot[ww][e]; }
    }
    __syncthreads();
    int off[NEXP];
#pragma unroll
    for (int e = 0; e < NEXP; e++) off[e] = wexcl[w][e] + inc[e] - cnt[e];
#pragma unroll
    for (int i = 0; i < PER; i++) {
        int e = myexp[i];
        int p = off[e]++;
        int s = base + i;
        g_pos[s] = p;
        if (p < CAP) {
            int n = s & (NTOK - 1);
            g_s2t[e * CAP + p] = n;
        }
    }
}

// ---------------- bf16x3 mma GEMM ----------------
#define BM 128
#define BN 128
#define BK 16
#define BKP 20    // A smem pad
#define BNP 132   // B smem pad: k-stride 2 rows -> conflict-free fragment reads
#define NSTAGE 3

__device__ __forceinline__ void cp16(uint32_t dst, const void* src, int bytes) {
    asm volatile("cp.async.cg.shared.global [%0], [%1], 16, %2;\n"
                 :: "r"(dst), "l"(src), "r"(bytes));
}
__device__ __forceinline__ void cp_commit() { asm volatile("cp.async.commit_group;\n" ::); }
__device__ __forceinline__ void cp_wait1()  { asm volatile("cp.async.wait_group 1;\n" ::); }

__device__ __forceinline__ void mma_bf16(float* d, const uint32_t* a, const uint32_t* b) {
    asm volatile(
        "mma.sync.aligned.m16n8k16.row.col.f32.bf16.bf16.f32 "
        "{%0,%1,%2,%3}, {%4,%5,%6,%7}, {%8,%9}, {%0,%1,%2,%3};\n"
        : "+f"(d[0]), "+f"(d[1]), "+f"(d[2]), "+f"(d[3])
        : "r"(a[0]), "r"(a[1]), "r"(a[2]), "r"(a[3]), "r"(b[0]), "r"(b[1]));
}

// split two fp32 -> packed bf16x2 hi + packed bf16x2 lo residual
__device__ __forceinline__ void bf16x2_split(float vx, float vy, uint32_t& hi, uint32_t& lo) {
    __nv_bfloat162 h = __floats2bfloat162_rn(vx, vy);
    hi = *reinterpret_cast<uint32_t*>(&h);
    float rx = vx - __bfloat162float(h.x);
    float ry = vy - __bfloat162float(h.y);
    __nv_bfloat162 l = __floats2bfloat162_rn(rx, ry);
    lo = *reinterpret_cast<uint32_t*>(&l);
}

// PHASE1: A = gather(x) via g_s2t, B = fc1_w, C = g_h, relu(+bias)
// PHASE2: A = g_h,                B = fc2_w, C = g_y, +bias
template<int KD, int ND, bool PHASE1>
__global__ void __launch_bounds__(256) gemm_kernel(
    const float* __restrict__ Ax,
    const float* __restrict__ B,
    const float* __restrict__ bias)
{
    extern __shared__ float smem[];
    float* As = smem;                          // [NSTAGE][BM][BKP]
    float* Bs = smem + NSTAGE * BM * BKP;      // [NSTAGE][BK][BNP]

    const int e  = blockIdx.z;
    const int m0 = blockIdx.y * BM;
    const int n0 = blockIdx.x * BN;
    const float* A  = PHASE1 ? Ax : (const float*)g_h;
    const float* Be = B + (size_t)e * KD * ND;
    float* Ce       = (PHASE1 ? g_h : g_y) + (size_t)e * CAP * ND;
    const float* be = bias + (size_t)e * ND;

    const int tid = threadIdx.x;
    uint32_t as_base = (uint32_t)__cvta_generic_to_shared(As);
    uint32_t bs_base = (uint32_t)__cvta_generic_to_shared(Bs);

    const float* aptr[2]; int abytes[2]; uint32_t adst[2];
#pragma unroll
    for (int i = 0; i < 2; i++) {
        int c = tid + i * 256;
        int row = c >> 2;
        int kc  = (c & 3) * 4;
        adst[i] = as_base + (uint32_t)((row * BKP + kc) * 4);
        if (PHASE1) {
            int tok = g_s2t[e * CAP + m0 + row];
            abytes[i] = (tok >= 0) ? 16 : 0;
            aptr[i] = (tok >= 0) ? (A + (size_t)tok * KD + kc) : A;
        } else {
            abytes[i] = 16;
            aptr[i] = A + (size_t)(e * CAP + m0 + row) * KD + kc;
        }
    }
    const float* bptr[2]; uint32_t bdst[2];
#pragma unroll
    for (int i = 0; i < 2; i++) {
        int c = tid + i * 256;
        int kr = c >> 5;
        int nc = (c & 31) * 4;
        bdst[i] = bs_base + (uint32_t)((kr * BNP + nc) * 4);
        bptr[i] = Be + (size_t)kr * ND + n0 + nc;
    }
    const uint32_t aStride = BM * BKP * 4;
    const uint32_t bStride = BK * BNP * 4;

    auto load_stage = [&](int buf, int kt) {
#pragma unroll
        for (int i = 0; i < 2; i++)
            cp16(adst[i] + buf * aStride, aptr[i] + (size_t)kt * BK, abytes[i]);
#pragma unroll
        for (int i = 0; i < 2; i++)
            cp16(bdst[i] + buf * bStride, bptr[i] + (size_t)kt * BK * ND, 16);
        cp_commit();
    };

    const int warp = tid >> 5, lane = tid & 31;
    const int wm = warp >> 2, wn = warp & 3;   // 2 x 4 warps
    const int mb = wm * 64, nb = wn * 32;      // warp tile 64x32
    const int lr = lane >> 2, lc = lane & 3;

    float acc[4][4][4];
#pragma unroll
    for (int mi = 0; mi < 4; mi++)
#pragma unroll
        for (int ni = 0; ni < 4; ni++)
#pragma unroll
            for (int r = 0; r < 4; r++) acc[mi][ni][r] = 0.f;

    const int KT = KD / BK;
    load_stage(0, 0);
    load_stage(1, 1);

    for (int kt = 0; kt < KT; kt++) {
        cp_wait1();
        __syncthreads();
        int buf = kt % NSTAGE;
        if (kt + 2 < KT) load_stage((kt + 2) % NSTAGE, kt + 2);

        const float* Ab = As + buf * BM * BKP;
        const float* Bb = Bs + buf * BK * BNP;

        // A fragments: m16n8k16 layout. rows lr, lr+8; k = 2lc..2lc+1 and +8
        uint32_t afh[4][4], afl[4][4];
#pragma unroll
        for (int mi = 0; mi < 4; mi++) {
            const float* p = Ab + (mb + mi * 16 + lr) * BKP;
            float2 x0 = *(const float2*)(p + 2 * lc);
            float2 x1 = *(const float2*)(p + 8 * BKP + 2 * lc);
            float2 x2 = *(const float2*)(p + 2 * lc + 8);
            float2 x3 = *(const float2*)(p + 8 * BKP + 2 * lc + 8);
            bf16x2_split(x0.x, x0.y, afh[mi][0], afl[mi][0]);
            bf16x2_split(x1.x, x1.y, afh[mi][1], afl[mi][1]);
            bf16x2_split(x2.x, x2.y, afh[mi][2], afl[mi][2]);
            bf16x2_split(x3.x, x3.y, afh[mi][3], afl[mi][3]);
        }
        // B fragments: col = nb+ni*8+lr, k rows 2lc,2lc+1 and +8,+9
        uint32_t bfh[4][2], bfl[4][2];
#pragma unroll
        for (int ni = 0; ni < 4; ni++) {
            const float* q = Bb + nb + ni * 8 + lr;
            float b00 = q[(2 * lc) * BNP];
            float b01 = q[(2 * lc + 1) * BNP];
            float b10 = q[(2 * lc + 8) * BNP];
            float b11 = q[(2 * lc + 9) * BNP];
            bf16x2_split(b00, b01, bfh[ni][0], bfl[ni][0]);
            bf16x2_split(b10, b11, bfh[ni][1], bfl[ni][1]);
        }
#pragma unroll
        for (int mi = 0; mi < 4; mi++)
#pragma unroll
            for (int ni = 0; ni < 4; ni++) {
                mma_bf16(acc[mi][ni], afh[mi], bfl[ni]);  // hi*lo
                mma_bf16(acc[mi][ni], afl[mi], bfh[ni]);  // lo*hi
                mma_bf16(acc[mi][ni], afh[mi], bfh[ni]);  // hi*hi
            }
        __syncthreads();
    }

    // epilogue: +bias (, relu), store fp32
#pragma unroll
    for (int mi = 0; mi < 4; mi++) {
        int r = m0 + mb + mi * 16 + lr;
#pragma unroll
        for (int ni = 0; ni < 4; ni++) {
            int cb = n0 + nb + ni * 8 + 2 * lc;
            float b0 = be[cb], b1 = be[cb + 1];
            float v0 = acc[mi][ni][0] + b0, v1 = acc[mi][ni][1] + b1;
            float v2 = acc[mi][ni][2] + b0, v3 = acc[mi][ni][3] + b1;
            if (PHASE1) {
                v0 = fmaxf(v0, 0.f); v1 = fmaxf(v1, 0.f);
                v2 = fmaxf(v2, 0.f); v3 = fmaxf(v3, 0.f);
            }
            *(float2*)&Ce[(size_t)r * ND + cb]       = make_float2(v0, v1);
            *(float2*)&Ce[(size_t)(r + 8) * ND + cb] = make_float2(v2, v3);
        }
    }
}

// ---------------- combine: out[n,:] = sum_slot topv * y[flat_idx,:] ----------------
__global__ void combine_kernel(float* __restrict__ out) {
    int n = blockIdx.x, tid = threadIdx.x;
    float4 acc = make_float4(0.f, 0.f, 0.f, 0.f);
#pragma unroll
    for (int slot = 0; slot < TOPK; slot++) {
        int p = g_pos[slot * NTOK + n];
        if (p < CAP) {
            float v = g_topv[n * 2 + slot];
            int e = g_topi[n * 2 + slot];
            const float4* row = (const float4*)(g_y + (size_t)(e * CAP + p) * DDIM);
            float4 f = row[tid];
            acc.x += v * f.x; acc.y += v * f.y; acc.z += v * f.z; acc.w += v * f.w;
        }
    }
    ((float4*)(out + (size_t)n * DDIM))[tid] = acc;
}

// ---------------- aux loss ----------------
__global__ void aux_kernel(float* __restrict__ out, int out_size) {
    __shared__ float s[256];
    int tid = threadIdx.x;
    float p[NEXP];
#pragma unroll
    for (int e = 0; e < NEXP; e++) p[e] = 0.f;
    for (int i = tid; i < NTOK; i += 256)
#pragma unroll
        for (int e = 0; e < NEXP; e++) p[e] += g_scores[i * NEXP + e];

    float total = 0.f;
#pragma unroll
    for (int e = 0; e < NEXP; e++) {
        s[tid] = p[e];
        __syncthreads();
        for (int st = 128; st > 0; st >>= 1) {
            if (tid < st) s[tid] += s[tid + st];
            __syncthreads();
        }
        if (tid == 0) {
            float me = s[0] / (float)NTOK;
            float ce = (float)g_ce[e] / (float)NTOK;
            total += me * ce;
        }
        __syncthreads();
    }
    if (tid == 0) {
        float laux = (float)NEXP * total;
        for (long i = (long)NTOK * DDIM; i < (long)out_size; i++) out[i] = laux;
    }
}

// ---------------- launch ----------------
extern "C" void kernel_launch(void* const* d_in, const int* in_sizes, int n_in,
                              void* d_out, int out_size) {
    const float* x    = (const float*)d_in[0];
    const float* wg   = (const float*)d_in[1];
    const float* fc1w = (const float*)d_in[2];
    const float* fc1b = (const float*)d_in[3];
    const float* fc2w = (const float*)d_in[4];
    const float* fc2b = (const float*)d_in[5];
    float* out = (float*)d_out;
    (void)in_sizes; (void)n_in;

    const int smem_bytes = (NSTAGE * BM * BKP + NSTAGE * BK * BNP) * 4;
    static bool attr_done = false;
    if (!attr_done) {
        cudaFuncSetAttribute(gemm_kernel<DDIM, HDIM, true >,
                             cudaFuncAttributeMaxDynamicSharedMemorySize, smem_bytes);
        cudaFuncSetAttribute(gemm_kernel<HDIM, DDIM, false>,
                             cudaFuncAttributeMaxDynamicSharedMemorySize, smem_bytes);
        attr_done = true;
    }

    init_kernel<<<(NEXP * CAP + 255) / 256, 256>>>();
    gate_kernel<<<NTOK / 8, 256>>>(x, wg);
    route_kernel<<<1, 512>>>();
    gemm_kernel<DDIM, HDIM, true ><<<dim3(HDIM / BN, CAP / BM, NEXP), 256, smem_bytes>>>(x, fc1w, fc1b);
    gemm_kernel<HDIM, DDIM, false><<<dim3(DDIM / BN, CAP / BM, NEXP), 256, smem_bytes>>>(x, fc2w, fc2b);
    combine_kernel<<<NTOK, 256>>>(out);
    aux_kernel<<<1, 256>>>(out, out_size);
}